// round 1
// baseline (speedup 1.0000x reference)
#include <cuda_runtime.h>
#include <cstddef>

// Problem constants (fixed shapes from reference setup_inputs)
constexpr int BB = 4;      // batch
constexpr int GG = 9;      // groups
constexpr int DD = 16;     // channels per group
constexpr int CC = GG * DD;  // 144
constexpr int NN = 16384;  // points
constexpr int KK = 16;     // knn neighbors

constexpr int PTS = BB * GG * NN;  // 589824 points total

// Scratch: point-major transposed copies of queryandkey and value.
// Layout: [(b*GG+g)*NN + n]*DD + dd  (each point's 16-float vector contiguous, 64B)
__device__ float g_qT[(size_t)PTS * DD];
__device__ float g_vT[(size_t)PTS * DD];

// ---------------------------------------------------------------------------
// Transpose kernel: (B, C, N) channel-major -> (B*G*N, 16) point-major.
// One thread per point, handles both q and v.
// Reads are coalesced across the warp (fixed dd, consecutive n).
// Writes are 4x STG.128 per array into a contiguous 2KB region per warp.
// ---------------------------------------------------------------------------
__global__ void transpose_kernel(const float* __restrict__ qk,
                                 const float* __restrict__ val) {
    int p = blockIdx.x * blockDim.x + threadIdx.x;
    if (p >= PTS) return;
    int n  = p % NN;
    int bg = p / NN;
    int g  = bg % GG;
    int b  = bg / GG;

    size_t src_off = ((size_t)b * CC + (size_t)g * DD) * NN + n;
    const float* __restrict__ qs = qk + src_off;
    const float* __restrict__ vs = val + src_off;

    float tq[DD], tv[DD];
#pragma unroll
    for (int dd = 0; dd < DD; dd++) {
        tq[dd] = qs[(size_t)dd * NN];
        tv[dd] = vs[(size_t)dd * NN];
    }

    float4* dq = reinterpret_cast<float4*>(g_qT + (size_t)p * DD);
    float4* dv = reinterpret_cast<float4*>(g_vT + (size_t)p * DD);
#pragma unroll
    for (int i = 0; i < 4; i++) {
        dq[i] = make_float4(tq[4*i+0], tq[4*i+1], tq[4*i+2], tq[4*i+3]);
        dv[i] = make_float4(tv[4*i+0], tv[4*i+1], tv[4*i+2], tv[4*i+3]);
    }
}

// ---------------------------------------------------------------------------
// Main attention kernel: one thread per (b, g, n) point.
//  - load q vec (4x float4, contiguous 64B)
//  - gather 16 neighbor key vecs (64B each), dot -> logits
//  - softmax over K=16 (fast __expf)
//  - gather 16 neighbor value vecs, weighted accumulate
//  - scatter-add weights into centrality (global red.add)
//  - write feat back in (B, C, N) layout (coalesced per dd across warp)
// ---------------------------------------------------------------------------
__global__ void attn_kernel(const int* __restrict__ idx,
                            float* __restrict__ out) {
    int p = blockIdx.x * blockDim.x + threadIdx.x;
    if (p >= PTS) return;
    int n  = p % NN;
    int bg = p / NN;           // = b*GG + g
    int g  = bg % GG;
    int b  = bg / GG;

    // Self query vector (64B contiguous)
    const float4* __restrict__ qv =
        reinterpret_cast<const float4*>(g_qT + (size_t)p * DD);
    float4 q0 = qv[0], q1 = qv[1], q2 = qv[2], q3 = qv[3];

    // Neighbor indices: (B, N, K) -> 16 ints contiguous (64B)
    const int4* __restrict__ ip =
        reinterpret_cast<const int4*>(idx + ((size_t)b * NN + n) * KK);
    int4 i0 = ip[0], i1 = ip[1], i2 = ip[2], i3 = ip[3];
    int nb[KK] = {i0.x, i0.y, i0.z, i0.w,
                  i1.x, i1.y, i1.z, i1.w,
                  i2.x, i2.y, i2.z, i2.w,
                  i3.x, i3.y, i3.z, i3.w};

    const size_t slice = (size_t)bg * NN;  // point-index base of this (b,g) slice

    // Pass 1: gather keys, compute logits
    float logit[KK];
#pragma unroll
    for (int k = 0; k < KK; k++) {
        const float4* __restrict__ kv =
            reinterpret_cast<const float4*>(g_qT + (slice + (size_t)nb[k]) * DD);
        float4 k0 = kv[0], k1 = kv[1], k2 = kv[2], k3 = kv[3];
        float d = q0.x * k0.x + q0.y * k0.y + q0.z * k0.z + q0.w * k0.w;
        d += q1.x * k1.x + q1.y * k1.y + q1.z * k1.z + q1.w * k1.w;
        d += q2.x * k2.x + q2.y * k2.y + q2.z * k2.z + q2.w * k2.w;
        d += q3.x * k3.x + q3.y * k3.y + q3.z * k3.z + q3.w * k3.w;
        logit[k] = d;
    }

    // Softmax over K
    float m = logit[0];
#pragma unroll
    for (int k = 1; k < KK; k++) m = fmaxf(m, logit[k]);
    float s = 0.0f;
#pragma unroll
    for (int k = 0; k < KK; k++) {
        float e = __expf(logit[k] - m);
        logit[k] = e;
        s += e;
    }
    float inv = __fdividef(1.0f, s);

    // Pass 2: gather values, weighted accumulate + centrality scatter
    float4 a0 = make_float4(0.f, 0.f, 0.f, 0.f);
    float4 a1 = a0, a2 = a0, a3 = a0;
    float* __restrict__ cent = out + (size_t)BB * CC * NN + slice;
#pragma unroll
    for (int k = 0; k < KK; k++) {
        float w = logit[k] * inv;
        const float4* __restrict__ vv =
            reinterpret_cast<const float4*>(g_vT + (slice + (size_t)nb[k]) * DD);
        float4 v0 = vv[0], v1 = vv[1], v2 = vv[2], v3 = vv[3];
        a0.x += w * v0.x; a0.y += w * v0.y; a0.z += w * v0.z; a0.w += w * v0.w;
        a1.x += w * v1.x; a1.y += w * v1.y; a1.z += w * v1.z; a1.w += w * v1.w;
        a2.x += w * v2.x; a2.y += w * v2.y; a2.z += w * v2.z; a2.w += w * v2.w;
        a3.x += w * v3.x; a3.y += w * v3.y; a3.z += w * v3.z; a3.w += w * v3.w;
        atomicAdd(cent + nb[k], w);   // no return value used -> REDG
    }

    // Write feat in (B, C, N) layout: coalesced across warp for each dd
    float* __restrict__ fo = out + ((size_t)b * CC + (size_t)g * DD) * NN + n;
    float acc[DD] = {a0.x, a0.y, a0.z, a0.w,
                     a1.x, a1.y, a1.z, a1.w,
                     a2.x, a2.y, a2.z, a2.w,
                     a3.x, a3.y, a3.z, a3.w};
#pragma unroll
    for (int dd = 0; dd < DD; dd++) {
        fo[(size_t)dd * NN] = acc[dd];
    }
}

extern "C" void kernel_launch(void* const* d_in, const int* in_sizes, int n_in,
                              void* d_out, int out_size) {
    const float* qk  = (const float*)d_in[0];   // queryandkey (B, C, N) f32
    const float* val = (const float*)d_in[1];   // value       (B, C, N) f32
    const int*   idx = (const int*)d_in[2];     // idx_knn     (B, N, K) i32
    float* out = (float*)d_out;                 // [feat (B,C,N) | cent (B,G,N)]

    // Zero the centrality region (d_out is poisoned to 0xAA before timing)
    cudaMemsetAsync(out + (size_t)BB * CC * NN, 0,
                    (size_t)BB * GG * NN * sizeof(float));

    const int threads = 256;
    const int blocks = (PTS + threads - 1) / threads;
    transpose_kernel<<<blocks, threads>>>(qk, val);
    attn_kernel<<<blocks, threads>>>(idx, out);
}

// round 2
// speedup vs baseline: 1.5380x; 1.5380x over previous
#include <cuda_runtime.h>
#include <cstddef>

// Problem constants (fixed shapes from reference setup_inputs)
constexpr int BB = 4;      // batch
constexpr int GG = 9;      // groups
constexpr int DD = 16;     // channels per group
constexpr int CC = GG * DD;  // 144
constexpr int NN = 16384;  // points
constexpr int KK = 16;     // knn neighbors

constexpr int PTS = BB * GG * NN;  // 589824 points total

// Scratch: interleaved point-major copy of queryandkey and value.
// Per point: 32 floats = [16 q floats | 16 v floats] = 128 bytes = one L2/L1 line.
__device__ float g_qv[(size_t)PTS * 32];

// ---------------------------------------------------------------------------
// Transpose kernel: (B, C, N) channel-major -> interleaved (B*G*N, 32).
// One thread per point. Reads coalesced across the warp (fixed dd,
// consecutive n); writes 8x STG.128 into the thread's own 128B line.
// ---------------------------------------------------------------------------
__global__ void transpose_kernel(const float* __restrict__ qk,
                                 const float* __restrict__ val) {
    int p = blockIdx.x * blockDim.x + threadIdx.x;
    if (p >= PTS) return;
    int n  = p % NN;
    int bg = p / NN;
    int g  = bg % GG;
    int b  = bg / GG;

    size_t src_off = ((size_t)b * CC + (size_t)g * DD) * NN + n;
    const float* __restrict__ qs = qk + src_off;
    const float* __restrict__ vs = val + src_off;

    float tq[DD], tv[DD];
#pragma unroll
    for (int dd = 0; dd < DD; dd++) {
        tq[dd] = qs[(size_t)dd * NN];
        tv[dd] = vs[(size_t)dd * NN];
    }

    float4* dst = reinterpret_cast<float4*>(g_qv + (size_t)p * 32);
#pragma unroll
    for (int i = 0; i < 4; i++)
        dst[i] = make_float4(tq[4*i+0], tq[4*i+1], tq[4*i+2], tq[4*i+3]);
#pragma unroll
    for (int i = 0; i < 4; i++)
        dst[4 + i] = make_float4(tv[4*i+0], tv[4*i+1], tv[4*i+2], tv[4*i+3]);
}

// ---------------------------------------------------------------------------
// Main attention kernel: FOUR threads per (b, g, n) point.
// Lane vl = tid&3 owns channels [4*vl, 4*vl+4).
// For each neighbor, the 4 lanes load 4 consecutive float4s of the 64B
// neighbor vector -> coalesced into ONE L1 wavefront returning 64 useful
// bytes (vs 4 wavefronts x 16B in the 1-thread-per-point version).
// Partial dot products are reduced across the 4 lanes with shfl.xor.
// ---------------------------------------------------------------------------
__global__ void attn_kernel(const int* __restrict__ idx,
                            float* __restrict__ out) {
    int t  = blockIdx.x * blockDim.x + threadIdx.x;
    int p  = t >> 2;          // point id
    int vl = t & 3;           // quarter-vector lane
    if (p >= PTS) return;
    int n  = p % NN;
    int bg = p / NN;          // = b*GG + g
    int g  = bg % GG;
    int b  = bg / GG;

    // Self query quarter (16B of the point's 128B line)
    const float4* __restrict__ base =
        reinterpret_cast<const float4*>(g_qv + (size_t)p * 32);
    float4 q = base[vl];

    // Neighbor indices: (B, N, K) -> 16 ints contiguous (64B).
    // All 4 lanes of a point load the same line (L1 broadcast).
    const int4* __restrict__ ip =
        reinterpret_cast<const int4*>(idx + ((size_t)b * NN + n) * KK);
    int4 i0 = ip[0], i1 = ip[1], i2 = ip[2], i3 = ip[3];
    int nb[KK] = {i0.x, i0.y, i0.z, i0.w,
                  i1.x, i1.y, i1.z, i1.w,
                  i2.x, i2.y, i2.z, i2.w,
                  i3.x, i3.y, i3.z, i3.w};

    const size_t slice = (size_t)bg * NN;  // point-index base of this (b,g) slice

    // Pass 1: cooperative key gather + partial dots + 4-lane reduction
    float logit[KK];
#pragma unroll
    for (int k = 0; k < KK; k++) {
        const float4* __restrict__ kv =
            reinterpret_cast<const float4*>(g_qv + (slice + (size_t)nb[k]) * 32);
        float4 kq = kv[vl];
        float d = q.x * kq.x + q.y * kq.y + q.z * kq.z + q.w * kq.w;
        d += __shfl_xor_sync(0xffffffffu, d, 1);
        d += __shfl_xor_sync(0xffffffffu, d, 2);
        logit[k] = d;   // full dot, replicated across the 4 lanes
    }

    // Softmax over K (replicated per lane — cheap FMA work)
    float m = logit[0];
#pragma unroll
    for (int k = 1; k < KK; k++) m = fmaxf(m, logit[k]);
    float s = 0.0f;
#pragma unroll
    for (int k = 0; k < KK; k++) {
        float e = __expf(logit[k] - m);
        logit[k] = e;
        s += e;
    }
    float inv = __fdividef(1.0f, s);

    // Pass 2: cooperative value gather (+64B into the SAME 128B line as the
    // key -> likely L1-resident), weighted accumulate + centrality scatter.
    float4 acc = make_float4(0.f, 0.f, 0.f, 0.f);
    float* __restrict__ cent = out + (size_t)BB * CC * NN + slice;
#pragma unroll
    for (int k = 0; k < KK; k++) {
        float w = logit[k] * inv;
        const float4* __restrict__ vv =
            reinterpret_cast<const float4*>(g_qv + (slice + (size_t)nb[k]) * 32 + 16);
        float4 v = vv[vl];
        acc.x += w * v.x; acc.y += w * v.y; acc.z += w * v.z; acc.w += w * v.w;
        if (vl == 0) atomicAdd(cent + nb[k], w);   // no return -> REDG
    }

    // Write feat quarter in (B, C, N) layout.
    float* __restrict__ fo =
        out + ((size_t)b * CC + (size_t)g * DD + (size_t)vl * 4) * NN + n;
    fo[0]            = acc.x;
    fo[(size_t)NN]   = acc.y;
    fo[(size_t)2*NN] = acc.z;
    fo[(size_t)3*NN] = acc.w;
}

extern "C" void kernel_launch(void* const* d_in, const int* in_sizes, int n_in,
                              void* d_out, int out_size) {
    const float* qk  = (const float*)d_in[0];   // queryandkey (B, C, N) f32
    const float* val = (const float*)d_in[1];   // value       (B, C, N) f32
    const int*   idx = (const int*)d_in[2];     // idx_knn     (B, N, K) i32
    float* out = (float*)d_out;                 // [feat (B,C,N) | cent (B,G,N)]

    // Zero the centrality region (d_out is poisoned to 0xAA before timing)
    cudaMemsetAsync(out + (size_t)BB * CC * NN, 0,
                    (size_t)BB * GG * NN * sizeof(float));

    const int threads = 256;
    {
        const int blocks = (PTS + threads - 1) / threads;
        transpose_kernel<<<blocks, threads>>>(qk, val);
    }
    {
        const int total = PTS * 4;   // 4 threads per point
        const int blocks = (total + threads - 1) / threads;
        attn_kernel<<<blocks, threads>>>(idx, out);
    }
}